// round 14
// baseline (speedup 1.0000x reference)
#include <cuda_runtime.h>

#define B_   64
#define LX_  512
#define LY_  512
#define DIM_ 64
#define BIGF 1e30f

// Pair-major scratch (PROVEN in R10):
//   g_Dp[PAD2 + b*(256*512) + m*512 + i] = {D[i][2m], D[i][2m+1]}
// Padded both sides so the DP prefetch ring may harmlessly over-read.
#define PAD2 32768
__device__ float2 g_Dp[2 * PAD2 + (size_t)B_ * 256 * 512];

typedef unsigned long long u64;

__device__ __forceinline__ u64 pack2(float lo, float hi) {
    u64 r; asm("mov.b64 %0,{%1,%2};" : "=l"(r) : "f"(lo), "f"(hi)); return r;
}
__device__ __forceinline__ u64 ffma2(u64 a, u64 b, u64 c) {
    u64 d; asm("fma.rn.f32x2 %0,%1,%2,%3;" : "=l"(d) : "l"(a), "l"(b), "l"(c)); return d;
}
__device__ __forceinline__ float2 unpack2(u64 v) {
    float2 f; asm("mov.b64 {%0,%1},%2;" : "=f"(f.x), "=f"(f.y) : "l"(v)); return f;
}
__device__ __forceinline__ float ex2_approx(float x) {
    float r; asm("ex2.approx.ftz.f32 %0,%1;" : "=f"(r) : "f"(x)); return r;
}
__device__ __forceinline__ float lg2_approx(float x) {
    float r; asm("lg2.approx.ftz.f32 %0,%1;" : "=f"(r) : "f"(x)); return r;
}
__device__ __forceinline__ float softmin3(float a, float b, float c) {
    const float L2E = 1.44269504f;
    const float LN2 = 0.69314718f;
    float m  = fminf(fminf(a, b), c);
    float mc = m * L2E;
    float ea = ex2_approx(fmaf(-L2E, a, mc));
    float eb = ex2_approx(fmaf(-L2E, b, mc));
    float ec = ex2_approx(fmaf(-L2E, c, mc));
    return fmaf(-LN2, lg2_approx((ea + eb) + ec), m);
}

#define TP 132

// ---------------------------------------------------------------------------
// Kernel 1: batched pairwise squared-L2 — EXACT R10 version (proven),
// pair-major writeout.
// ---------------------------------------------------------------------------
__global__ __launch_bounds__(256) void sdtw_gemm_kernel(
    const float* __restrict__ X, const float* __restrict__ Y)
{
    __shared__ float pool[2 * 32 * TP];
    float* Xs = pool;
    float* Ys = pool + 32 * TP;

    const int b  = blockIdx.z;
    const int i0 = blockIdx.y * 128;
    const int j0 = blockIdx.x * 128;
    const int tid = threadIdx.x;
    const int tx = tid & 15;
    const int ty = tid >> 4;

    const float* Xb = X + ((size_t)b * LX_ + i0) * DIM_;
    const float* Yb = Y + ((size_t)b * LY_ + j0) * DIM_;

    u64 acc2[8][4];
    u64 xn2[4], yn2[4];
    const u64 z = pack2(0.f, 0.f);
#pragma unroll
    for (int r = 0; r < 8; ++r)
#pragma unroll
        for (int p = 0; p < 4; ++p) acc2[r][p] = z;
#pragma unroll
    for (int p = 0; p < 4; ++p) { xn2[p] = z; yn2[p] = z; }

#pragma unroll 1
    for (int kh = 0; kh < 2; ++kh) {
        __syncthreads();
#pragma unroll
        for (int it = 0; it < 4; ++it) {
            int f4  = it * 256 + tid;
            int row = f4 >> 3;
            int k4  = (f4 & 7) << 2;
            float4 xv = *(const float4*)(Xb + row * DIM_ + kh * 32 + k4);
            Xs[(k4 + 0) * TP + row] = xv.x; Xs[(k4 + 1) * TP + row] = xv.y;
            Xs[(k4 + 2) * TP + row] = xv.z; Xs[(k4 + 3) * TP + row] = xv.w;
            float4 yv = *(const float4*)(Yb + row * DIM_ + kh * 32 + k4);
            Ys[(k4 + 0) * TP + row] = yv.x; Ys[(k4 + 1) * TP + row] = yv.y;
            Ys[(k4 + 2) * TP + row] = yv.z; Ys[(k4 + 3) * TP + row] = yv.w;
        }
        __syncthreads();

#pragma unroll 8
        for (int k = 0; k < 32; ++k) {
            float4 xa = *(const float4*)&Xs[k * TP + ty * 8];
            float4 xb = *(const float4*)&Xs[k * TP + ty * 8 + 4];
            float4 ya = *(const float4*)&Ys[k * TP + tx * 8];
            float4 yb = *(const float4*)&Ys[k * TP + tx * 8 + 4];
            u64 yp[4] = { pack2(ya.x, ya.y), pack2(ya.z, ya.w),
                          pack2(yb.x, yb.y), pack2(yb.z, yb.w) };
            float xs[8] = {xa.x, xa.y, xa.z, xa.w, xb.x, xb.y, xb.z, xb.w};
#pragma unroll
            for (int r = 0; r < 8; ++r) {
                u64 xp = pack2(xs[r], xs[r]);
#pragma unroll
                for (int p = 0; p < 4; ++p)
                    acc2[r][p] = ffma2(xp, yp[p], acc2[r][p]);
            }
            u64 xq[4] = { pack2(xa.x, xa.y), pack2(xa.z, xa.w),
                          pack2(xb.x, xb.y), pack2(xb.z, xb.w) };
#pragma unroll
            for (int p = 0; p < 4; ++p) {
                xn2[p] = ffma2(xq[p], xq[p], xn2[p]);
                yn2[p] = ffma2(yp[p], yp[p], yn2[p]);
            }
        }
    }

    float xn[8], yn[8], dres[8][8];
#pragma unroll
    for (int p = 0; p < 4; ++p) {
        float2 xv = unpack2(xn2[p]); xn[2*p] = xv.x; xn[2*p+1] = xv.y;
        float2 yv = unpack2(yn2[p]); yn[2*p] = yv.x; yn[2*p+1] = yv.y;
    }
#pragma unroll
    for (int r = 0; r < 8; ++r)
#pragma unroll
        for (int p = 0; p < 4; ++p) {
            float2 a = unpack2(acc2[r][p]);
            dres[r][2*p]   = fmaf(-2.0f, a.x, xn[r] + yn[2*p]);
            dres[r][2*p+1] = fmaf(-2.0f, a.y, xn[r] + yn[2*p+1]);
        }

    // Pair-major writeout per 64x64 quadrant via smem stage (EXACT R10).
    const int CP = 66;
    float* stage = pool;
    const int g  = tid >> 6;
    const int li = tid & 63;
#pragma unroll 1
    for (int q = 0; q < 4; ++q) {
        int qi = q >> 1, qj = q & 1;
        __syncthreads();
        if ((ty >> 3) == qi && (tx >> 3) == qj) {
            int r0 = (ty & 7) * 8, c0 = (tx & 7) * 8;
#pragma unroll
            for (int r = 0; r < 8; ++r)
#pragma unroll
                for (int c = 0; c < 8; ++c)
                    stage[(r0 + r) * CP + (c0 + c)] = dres[r][c];
        }
        __syncthreads();
        int i0q = i0 + qi * 64, j0q = j0 + qj * 64;
        float2* Dpb = g_Dp + PAD2 + (size_t)b * (256 * 512)
                    + (size_t)(j0q >> 1) * 512 + i0q;
#pragma unroll
        for (int ml = g; ml < 32; ml += 4) {
            float2 v;
            v.x = stage[li * CP + 2 * ml];
            v.y = stage[li * CP + 2 * ml + 1];
            Dpb[(size_t)ml * 512 + li] = v;
        }
    }
}

// ---------------------------------------------------------------------------
// Kernel 2: warp-pipelined soft-DTW wavefront — EXACT R10 dataflow
// (16 warps, 1 row/lane, 2 columns/step), reparameterized to C=8 / LAG=5:
// 111 phases x 8 step-slots = 888 slots (vs R10's 63 x 16 = 1008), same
// per-step body. Skew slack = 1 full barrier phase (same margin as R10).
// ---------------------------------------------------------------------------
__global__ __launch_bounds__(512) void sdtw_dp_kernel(float* __restrict__ out)
{
    __shared__ float2 bndp[16][256]; // bndp[w][m] = {R[32w+31][2m], R[32w+31][2m+1]}

    const int tid = threadIdx.x;
    const int w = tid >> 5;          // 0..15
    const int l = tid & 31;
    const int b = blockIdx.x;

    // Per-lane base: element for local step s lives at DW[s * 512].
    const float2* __restrict__ DW =
        g_Dp + PAD2 + (size_t)b * (256 * 512) + (32 * w + l) - (ptrdiff_t)l * 512;

    float c0 = BIGF;                              // own rc0 from prev step
    float a1 = BIGF;                              // own rc1 from prev step
    float prev_u1 = (tid == 0) ? 0.0f : BIGF;     // diag seed / prev step's up1

    float2 dring[8];                              // depth-8 prefetch ring
#pragma unroll
    for (int u = 0; u < 8; ++u) dring[u] = DW[(size_t)u * 512];

    __syncthreads();

    const int C   = 8;
    const int NCH = 36;              // ceil(287/8); covers local steps 0..287
    const int LAG = 5;
    const int P = 15 * LAG + NCH;    // 111 phases
    const float2* bprev = bndp[(w > 0) ? (w - 1) : 0];
    const bool lane0  = (l == 0);
    const bool w0     = (w == 0);
    const bool lane31 = (l == 31);

#pragma unroll 1
    for (int p = 0; p < P; ++p) {
        int q = p - LAG * w;
        if (q >= 0 && q < NCH) {                  // warp-uniform
            int s0 = q * C;
            int mb0 = (s0 > 255) ? 255 : s0;
            float2 bcur = bprev[mb0];             // {R[32w-1][2s], R[32w-1][2s+1]}
#pragma unroll
            for (int u = 0; u < C; ++u) {
                int s = s0 + u;
                float2 d = dring[u & 7];
                dring[u & 7] = DW[(size_t)(s + 8) * 512];   // refill (pad OK)

                // boundary prefetch, clamped WITHIN this chunk
                int sn = (u < C - 1) ? (s + 1) : s;
                int mbn = (sn > 255) ? 255 : sn;
                float2 bnext = bprev[mbn];        // warp-uniform broadcast

                float up0s = __shfl_up_sync(0xFFFFFFFFu, c0, 1);
                float up1s = __shfl_up_sync(0xFFFFFFFFu, a1, 1);
                float up0 = lane0 ? (w0 ? BIGF : bcur.x) : up0s;
                float up1 = lane0 ? (w0 ? BIGF : bcur.y) : up1s;

                int sl = s - l;
                bool valid = ((unsigned)sl <= 255u);

                // cell 0: j0 = 2(s-l)
                float rc0v = softmin3(up0, prev_u1, a1) + d.x;
                float rc0 = valid ? rc0v : BIGF;

                // cell 1: j1 = j0 + 1
                float rc1v = softmin3(up1, up0, rc0) + d.y;
                float rc1 = valid ? rc1v : BIGF;

                prev_u1 = up1;
                c0 = rc0;
                a1 = rc1;
                bcur = bnext;

                // single predicated STS.64 publish of bottom row pair
                if (lane31 && valid) bndp[w][sl] = make_float2(rc0, rc1);
            }
        }
        __syncthreads();
    }

    // R[511][511] = second element of warp 15's pair at m=255 (s=286).
    if (tid == 0) out[b] = bndp[15][255].y;
}

// ---------------------------------------------------------------------------
extern "C" void kernel_launch(void* const* d_in, const int* in_sizes, int n_in,
                              void* d_out, int out_size)
{
    (void)in_sizes; (void)n_in; (void)out_size;
    const float* X = (const float*)d_in[0];
    const float* Y = (const float*)d_in[1];
    float* out = (float*)d_out;

    dim3 gg(LY_ / 128, LX_ / 128, B_);
    sdtw_gemm_kernel<<<gg, 256>>>(X, Y);
    sdtw_dp_kernel<<<B_, 512>>>(out);
}